// round 15
// baseline (speedup 1.0000x reference)
#include <cuda_runtime.h>
#include <cuda_fp16.h>
#include <cmath>
#include <cstdint>

#define NN   50000
#define EE   800000
#define ETOT 850000
#define INC  128
#define HID  64
#define NH   4
#define HK   256
#define OUTC 40
#define NLAY 4
#define SB   13

// ---------------- device scratch ----------------
__device__ float  g_h[(size_t)NN * HID];
__device__ __half g_hh[(size_t)NN * HID];
__device__ __half g_agg[(size_t)NN * HK];
__device__ float  g_as[(size_t)NN * NH];
__device__ float  g_ad[(size_t)NN * NH];
__device__ float  g_wa[NLAY * 8 * HID];
__device__ __half g_wc[NLAY * NH * HID * HID];
__device__ __half g_wih[INC * HID];
__device__ __half g_woh[HID * 64];
__device__ int    g_deg[NN];
__device__ int    g_rowptr[NN + 1];
__device__ int    g_erank[ETOT];
__device__ int    g_csrc[ETOT];
__device__ int    g_bsum[16];

// ---------------- CSR build ----------------
__global__ void hist_kernel(const int* __restrict__ ei) {
    int e0 = (blockIdx.x * blockDim.x + threadIdx.x) * 4;
    if (e0 >= ETOT) return;
    if (e0 < EE) {
        int4 d4 = *(const int4*)(ei + EE + e0);
        int4 r4;
        r4.x = atomicAdd(&g_deg[d4.x], 1);
        r4.y = atomicAdd(&g_deg[d4.y], 1);
        r4.z = atomicAdd(&g_deg[d4.z], 1);
        r4.w = atomicAdd(&g_deg[d4.w], 1);
        __stcs((int4*)(g_erank + e0), r4);
    } else {
        #pragma unroll
        for (int k = 0; k < 4; k++) {
            int e = e0 + k;
            if (e >= ETOT) return;
            g_erank[e] = atomicAdd(&g_deg[e - EE], 1);
        }
    }
}

__global__ void scan1_kernel() {
    __shared__ int wsum[32];
    int t = threadIdx.x;
    int i0 = blockIdx.x * 4096 + t * 4;
    int4 v = make_int4(0, 0, 0, 0);
    if (i0 + 3 < NN) {
        v = *(const int4*)(g_deg + i0);
        *(int4*)(g_deg + i0) = make_int4(0, 0, 0, 0);
    } else {
        if (i0 + 0 < NN) { v.x = g_deg[i0 + 0]; g_deg[i0 + 0] = 0; }
        if (i0 + 1 < NN) { v.y = g_deg[i0 + 1]; g_deg[i0 + 1] = 0; }
        if (i0 + 2 < NN) { v.z = g_deg[i0 + 2]; g_deg[i0 + 2] = 0; }
        if (i0 + 3 < NN) { v.w = g_deg[i0 + 3]; g_deg[i0 + 3] = 0; }
    }
    int tot = v.x + v.y + v.z + v.w;
    int x = tot;
    #pragma unroll
    for (int s = 1; s < 32; s <<= 1) {
        int y = __shfl_up_sync(0xFFFFFFFFu, x, s);
        if ((t & 31) >= s) x += y;
    }
    if ((t & 31) == 31) wsum[t >> 5] = x;
    __syncthreads();
    if (t < 32) {
        int y = wsum[t];
        #pragma unroll
        for (int s = 1; s < 32; s <<= 1) {
            int z = __shfl_up_sync(0xFFFFFFFFu, y, s);
            if (t >= s) y += z;
        }
        wsum[t] = y;
    }
    __syncthreads();
    int excl = x - tot + ((t >= 32) ? wsum[(t >> 5) - 1] : 0);
    if (i0 + 3 < NN) {
        *(int4*)(g_rowptr + i0) =
            make_int4(excl, excl + v.x, excl + v.x + v.y, excl + v.x + v.y + v.z);
    } else {
        if (i0 + 0 < NN) g_rowptr[i0 + 0] = excl;
        if (i0 + 1 < NN) g_rowptr[i0 + 1] = excl + v.x;
        if (i0 + 2 < NN) g_rowptr[i0 + 2] = excl + v.x + v.y;
        if (i0 + 3 < NN) g_rowptr[i0 + 3] = excl + v.x + v.y + v.z;
    }
    if (t == 0) g_bsum[blockIdx.x] = wsum[31];
}

__global__ void scan3_kernel() {
    __shared__ int offs[SB];
    __shared__ int tot_sh;
    int t = threadIdx.x;
    if (t < 32) {
        int v = (t < SB) ? g_bsum[t] : 0;
        int x = v;
        #pragma unroll
        for (int s = 1; s < 32; s <<= 1) {
            int y = __shfl_up_sync(0xFFFFFFFFu, x, s);
            if (t >= s) x += y;
        }
        if (t < SB) offs[t] = x - v;
        if (t == 31) tot_sh = x;
    }
    __syncthreads();
    int off = offs[blockIdx.x];
    int i0 = blockIdx.x * 4096 + t * 4;
    if (i0 + 3 < NN) {
        int4 r = *(const int4*)(g_rowptr + i0);
        r.x += off; r.y += off; r.z += off; r.w += off;
        *(int4*)(g_rowptr + i0) = r;
    } else {
        for (int k = 0; k < 4; k++) {
            if (i0 + k < NN) g_rowptr[i0 + k] += off;
        }
    }
    if (blockIdx.x == 0 && t == 0) g_rowptr[NN] = tot_sh;
}

__global__ void scatter_kernel(const int* __restrict__ ei) {
    int e0 = (blockIdx.x * blockDim.x + threadIdx.x) * 4;
    if (e0 >= ETOT) return;
    if (e0 < EE) {
        int4 s4 = __ldcs((const int4*)(ei + e0));
        int4 d4 = __ldcs((const int4*)(ei + EE + e0));
        int4 r4 = __ldcs((const int4*)(g_erank + e0));
        __stcs(g_csrc + g_rowptr[d4.x] + r4.x, s4.x);
        __stcs(g_csrc + g_rowptr[d4.y] + r4.y, s4.y);
        __stcs(g_csrc + g_rowptr[d4.z] + r4.z, s4.z);
        __stcs(g_csrc + g_rowptr[d4.w] + r4.w, s4.w);
    } else {
        #pragma unroll
        for (int k = 0; k < 4; k++) {
            int e = e0 + k;
            if (e >= ETOT) return;
            int n = e - EE;
            __stcs(g_csrc + g_rowptr[n] + g_erank[e], n);
        }
    }
}

// ---------------- fused prep ----------------
__global__ void prep_kernel(const float* __restrict__ Wi,
                            const float* __restrict__ Wo,
                            const float* __restrict__ lin_W,
                            const float* __restrict__ att_src,
                            const float* __restrict__ att_dst) {
    int b = blockIdx.x, t = threadIdx.x;
    if (b < 32) {
        int i = b * 256 + t;
        if (i < INC * HID) g_wih[i] = __float2half(Wi[i]);
        if (i < HID * 64) {
            int k = i >> 6, c = i & 63;
            g_woh[i] = __float2half(c < OUTC ? Wo[k * OUTC + c] : 0.f);
        }
    } else if (b < 40) {
        int tid = (b - 32) * 256 + t;
        if (tid >= NLAY * 8 * HID) return;
        int k = tid & 63;
        int v = (tid >> 6) & 7;
        int l = tid >> 9;
        int h = v & 3;
        const float* att  = (v < 4) ? att_src : att_dst;
        const float* wrow = lin_W + (size_t)l * HID * HK + (size_t)k * HK + h * HID;
        const float* arow = att + l * HK + h * HID;
        float s = 0.f;
        #pragma unroll
        for (int c = 0; c < HID; c++) s += wrow[c] * arow[c];
        g_wa[tid] = s;
    } else {
        int tid = (b - 40) * 256 + t;
        if (tid >= NLAY * NH * HID * HID) return;
        int c = tid & 63;
        int k = (tid >> 6) & 63;
        int h = (tid >> 12) & 3;
        int l = tid >> 14;
        g_wc[tid] = __float2half(0.25f * lin_W[(size_t)l * HID * HK + (size_t)k * HK + h * HID + c]);
    }
}

// ---------------- MMA input GEMM + fused layer-0 alpha ----------------
__global__ void gemm_in(const float* __restrict__ x, const float* __restrict__ bi) {
    __shared__ alignas(16) char buf[49152];
    __half* Asm = (__half*)buf;
    __half* Bsm = (__half*)(buf + 32768);
    float*  Cs  = (float*)buf;
    float*  wa_sm = (float*)(buf + 47104);

    int t = threadIdx.x;
    int m0 = blockIdx.x << 7;
    #pragma unroll
    for (int i = 0; i < 8; i++) {
        int cid = t + i * 256;
        int r = cid >> 4, c = cid & 15;
        __half2 hv[4] = {};
        if (m0 + r < NN) {
            const float* src = x + (size_t)(m0 + r) * INC + (c << 3);
            float4 f0 = *(const float4*)src;
            float4 f1 = *(const float4*)(src + 4);
            hv[0] = __floats2half2_rn(f0.x, f0.y);
            hv[1] = __floats2half2_rn(f0.z, f0.w);
            hv[2] = __floats2half2_rn(f1.x, f1.y);
            hv[3] = __floats2half2_rn(f1.z, f1.w);
        }
        *(uint4*)(Asm + r * 128 + ((c ^ (r & 7)) << 3)) = *(uint4*)hv;
    }
    #pragma unroll
    for (int i = 0; i < 4; i++) {
        int cid = t + i * 256;
        int k = cid >> 3, c = cid & 7;
        uint4 v = *(const uint4*)(g_wih + k * 64 + (c << 3));
        *(uint4*)(Bsm + k * 64 + ((c ^ (k & 7)) << 3)) = v;
    }
    __syncthreads();

    int wid = t >> 5, lane = t & 31;
    int wm = (wid & 3) << 5;
    int wn = (wid >> 2) << 5;
    float c[2][4][4] = {};

    #pragma unroll
    for (int ks = 0; ks < 8; ks++) {
        uint32_t a[2][4];
        #pragma unroll
        for (int mt = 0; mt < 2; mt++) {
            int row = wm + (mt << 4) + (lane & 15);
            int chunk = (ks << 1) + (lane >> 4);
            uint32_t addr = (uint32_t)__cvta_generic_to_shared(
                Asm + row * 128 + ((chunk ^ (row & 7)) << 3));
            asm volatile("ldmatrix.sync.aligned.m8n8.x4.shared.b16 {%0,%1,%2,%3}, [%4];"
                         : "=r"(a[mt][0]), "=r"(a[mt][1]), "=r"(a[mt][2]), "=r"(a[mt][3])
                         : "r"(addr));
        }
        uint32_t b[4][2];
        #pragma unroll
        for (int nt2 = 0; nt2 < 2; nt2++) {
            int krow = (ks << 4) + (lane & 15);
            int nchunk = ((wn + (nt2 << 4)) >> 3) + (lane >> 4);
            uint32_t addr = (uint32_t)__cvta_generic_to_shared(
                Bsm + krow * 64 + ((nchunk ^ (krow & 7)) << 3));
            uint32_t r0, r1, r2, r3;
            asm volatile("ldmatrix.sync.aligned.m8n8.x4.trans.shared.b16 {%0,%1,%2,%3}, [%4];"
                         : "=r"(r0), "=r"(r1), "=r"(r2), "=r"(r3)
                         : "r"(addr));
            b[nt2 * 2 + 0][0] = r0; b[nt2 * 2 + 0][1] = r1;
            b[nt2 * 2 + 1][0] = r2; b[nt2 * 2 + 1][1] = r3;
        }
        #pragma unroll
        for (int mt = 0; mt < 2; mt++)
            #pragma unroll
            for (int nt = 0; nt < 4; nt++)
                asm volatile(
                    "mma.sync.aligned.m16n8k16.row.col.f32.f16.f16.f32 "
                    "{%0,%1,%2,%3},{%4,%5,%6,%7},{%8,%9},{%0,%1,%2,%3};"
                    : "+f"(c[mt][nt][0]), "+f"(c[mt][nt][1]),
                      "+f"(c[mt][nt][2]), "+f"(c[mt][nt][3])
                    : "r"(a[mt][0]), "r"(a[mt][1]), "r"(a[mt][2]), "r"(a[mt][3]),
                      "r"(b[nt][0]), "r"(b[nt][1]));
    }

    __syncthreads();
    #pragma unroll
    for (int i = 0; i < 2; i++)
        wa_sm[t + i * 256] = g_wa[t + i * 256];

    int rg = lane >> 2, cg = (lane & 3) << 1;
    #pragma unroll
    for (int nt = 0; nt < 4; nt++) {
        int col = wn + (nt << 3) + cg;
        float b0 = bi[col], b1 = bi[col + 1];
        #pragma unroll
        for (int mt = 0; mt < 2; mt++) {
            #pragma unroll
            for (int half_ = 0; half_ < 2; half_++) {
                int rl = wm + (mt << 4) + rg + half_ * 8;
                int r = m0 + rl;
                float v0 = c[mt][nt][half_ * 2 + 0] + b0;
                float v1 = c[mt][nt][half_ * 2 + 1] + b1;
                v0 = v0 > 0.f ? v0 : expm1f(v0);
                v1 = v1 > 0.f ? v1 : expm1f(v1);
                Cs[rl * 68 + col]     = v0;
                Cs[rl * 68 + col + 1] = v1;
                if (r < NN) {
                    *(float2*)(g_h + (size_t)r * HID + col) = make_float2(v0, v1);
                    *(__half2*)(g_hh + (size_t)r * HID + col) = __floats2half2_rn(v0, v1);
                }
            }
        }
    }
    __syncthreads();

    {
        int r = t >> 1, hs = t & 1;
        int n = m0 + r;
        if (n < NN) {
            const float* wv = wa_sm + hs * 4 * 64;
            float a0 = 0.f, a1 = 0.f, a2 = 0.f, a3 = 0.f;
            #pragma unroll
            for (int cc = 0; cc < 64; cc++) {
                float hv = Cs[r * 68 + cc];
                a0 += hv * wv[cc];
                a1 += hv * wv[64 + cc];
                a2 += hv * wv[128 + cc];
                a3 += hv * wv[192 + cc];
            }
            float* dst = (hs == 0 ? g_as : g_ad) + 4 * (size_t)n;
            *(float4*)dst = make_float4(a0, a1, a2, a3);
        }
    }
}

// ---------------- aggregation in h-space (R6 exact) ----------------
__global__ void agg_h_kernel() {
    __shared__ float sp[8][32][4];
    int wl   = threadIdx.x >> 5;
    int w    = (blockIdx.x * blockDim.x + threadIdx.x) >> 5;
    int lane = threadIdx.x & 31;
    if (w >= NN) return;

    float4 ad4 = *(const float4*)(g_ad + 4 * (size_t)w);

    float acc[4][2] = {};
    float denl[4] = {};
    int beg = g_rowptr[w], end = g_rowptr[w + 1];

    for (int base = beg; base < end; base += 32) {
        int idx = base + lane;
        bool valid = idx < end;
        int sv = valid ? g_csrc[idx] : 0;
        float4 as4 = *(const float4*)(g_as + 4 * (size_t)sv);
        float p0, p1, p2, p3;
        {
            float e0 = as4.x + ad4.x, e1 = as4.y + ad4.y;
            float e2 = as4.z + ad4.z, e3 = as4.w + ad4.w;
            e0 = e0 > 0.f ? e0 : 0.2f * e0;
            e1 = e1 > 0.f ? e1 : 0.2f * e1;
            e2 = e2 > 0.f ? e2 : 0.2f * e2;
            e3 = e3 > 0.f ? e3 : 0.2f * e3;
            p0 = valid ? __expf(e0) : 0.f;
            p1 = valid ? __expf(e1) : 0.f;
            p2 = valid ? __expf(e2) : 0.f;
            p3 = valid ? __expf(e3) : 0.f;
        }
        denl[0] += p0; denl[1] += p1; denl[2] += p2; denl[3] += p3;
        *(float4*)&sp[wl][lane][0] = make_float4(p0, p1, p2, p3);
        __syncwarp();

        int m = end - base; if (m > 32) m = 32;
        int j = 0;
        for (; j + 1 < m; j += 2) {
            int sA = __shfl_sync(0xFFFFFFFFu, sv, j);
            int sB = __shfl_sync(0xFFFFFFFFu, sv, j + 1);
            float4 pA = *(const float4*)&sp[wl][j][0];
            float4 pB = *(const float4*)&sp[wl][j + 1][0];
            __half2 hA = *(const __half2*)(g_hh + (size_t)sA * HID + 2 * lane);
            __half2 hB = *(const __half2*)(g_hh + (size_t)sB * HID + 2 * lane);
            float2 fA = __half22float2(hA);
            float2 fB = __half22float2(hB);
            acc[0][0] += pA.x * fA.x + pB.x * fB.x;
            acc[0][1] += pA.x * fA.y + pB.x * fB.y;
            acc[1][0] += pA.y * fA.x + pB.y * fB.x;
            acc[1][1] += pA.y * fA.y + pB.y * fB.y;
            acc[2][0] += pA.z * fA.x + pB.z * fB.x;
            acc[2][1] += pA.z * fA.y + pB.z * fB.y;
            acc[3][0] += pA.w * fA.x + pB.w * fB.x;
            acc[3][1] += pA.w * fA.y + pB.w * fB.y;
        }
        if (j < m) {
            int s = __shfl_sync(0xFFFFFFFFu, sv, j);
            float4 pj = *(const float4*)&sp[wl][j][0];
            __half2 hv = *(const __half2*)(g_hh + (size_t)s * HID + 2 * lane);
            float2 f = __half22float2(hv);
            acc[0][0] += pj.x * f.x; acc[0][1] += pj.x * f.y;
            acc[1][0] += pj.y * f.x; acc[1][1] += pj.y * f.y;
            acc[2][0] += pj.z * f.x; acc[2][1] += pj.z * f.y;
            acc[3][0] += pj.w * f.x; acc[3][1] += pj.w * f.y;
        }
        __syncwarp();
    }

    #pragma unroll
    for (int h = 0; h < 4; h++) {
        float d = denl[h];
        #pragma unroll
        for (int s = 16; s > 0; s >>= 1)
            d += __shfl_xor_sync(0xFFFFFFFFu, d, s);
        denl[h] = 1.f / (d + 1e-16f);
    }

    __half* ap = g_agg + (size_t)w * HK;
    #pragma unroll
    for (int h = 0; h < 4; h++) {
        *(__half2*)(ap + h * HID + 2 * lane) =
            __floats2half2_rn(acc[h][0] * denl[h], acc[h][1] * denl[h]);
    }
}

// ---------------- MMA head-mix GEMM (double-buffered) + epilogue + alpha + (last) output GEMM ----------------
// smem: AsmA [0,16384) AsmB [16384,32768) BsmA [32768,40960) BsmB [40960,49152) wa [49152,51200)
// after mainloop: Cs [0,34816); last-layer: Asm2 [36864,53248) Bsm2 [53248,61440)
__global__ void gemm_agg(const float* __restrict__ gat_b,
                         const float* __restrict__ ln_g,
                         const float* __restrict__ ln_b, int layer,
                         const float* __restrict__ bo, float* __restrict__ out,
                         int last) {
    extern __shared__ char buf[];
    float* Cs    = (float*)buf;
    float* wa_sm = (float*)(buf + 49152);

    int t  = threadIdx.x;
    int m0 = blockIdx.x << 7;
    int wid = t >> 5, lane = t & 31;
    int wm = (wid & 3) << 5;
    int wn = (wid >> 2) << 5;
    bool do_alpha = (layer + 1 < NLAY);

    if (do_alpha) {
        #pragma unroll
        for (int i = 0; i < 2; i++)
            wa_sm[t + i * 256] = g_wa[(layer + 1) * 512 + t + i * 256];
    }

    // per-thread load indices (fixed across heads)
    int ar[4], acs[4];   // A: 4 chunks per thread
    #pragma unroll
    for (int i = 0; i < 4; i++) {
        int cid = t + i * 256;
        ar[i] = cid >> 3; acs[i] = cid & 7;
    }
    int bk[2], bcs[2];   // B: 2 chunks per thread
    #pragma unroll
    for (int i = 0; i < 2; i++) {
        int cid = t + i * 256;
        bk[i] = cid >> 3; bcs[i] = cid & 7;
    }

    auto loadA = [&](int h, uint4* ra) {
        #pragma unroll
        for (int i = 0; i < 4; i++) {
            ra[i] = make_uint4(0, 0, 0, 0);
            if (m0 + ar[i] < NN)
                ra[i] = *(const uint4*)(g_agg + (size_t)(m0 + ar[i]) * HK + h * HID + (acs[i] << 3));
        }
    };
    auto loadB = [&](int h, uint4* rb) {
        const __half* wb = g_wc + (size_t)(layer * 4 + h) * HID * HID;
        #pragma unroll
        for (int i = 0; i < 2; i++)
            rb[i] = *(const uint4*)(wb + bk[i] * 64 + (bcs[i] << 3));
    };
    auto storeA = [&](int bsel, uint4* ra) {
        __half* Asm = (__half*)(buf + bsel * 16384);
        #pragma unroll
        for (int i = 0; i < 4; i++)
            *(uint4*)(Asm + ar[i] * 64 + ((acs[i] ^ (ar[i] & 7)) << 3)) = ra[i];
    };
    auto storeB = [&](int bsel, uint4* rb) {
        __half* Bsm = (__half*)(buf + 32768 + bsel * 8192);
        #pragma unroll
        for (int i = 0; i < 2; i++)
            *(uint4*)(Bsm + bk[i] * 64 + ((bcs[i] ^ (bk[i] & 7)) << 3)) = rb[i];
    };

    float c[2][4][4] = {};
    uint4 ra[4], rb[2];

    // prologue: head 0 -> buffer 0; prefetch head 1 into regs
    loadA(0, ra); loadB(0, rb);
    storeA(0, ra); storeB(0, rb);
    loadA(1, ra); loadB(1, rb);
    __syncthreads();

    for (int h = 0; h < 4; h++) {
        int cur = h & 1;
        if (h + 1 < 4) {
            storeA(cur ^ 1, ra); storeB(cur ^ 1, rb);   // prefetched head h+1
            if (h + 2 < 4) { loadA(h + 2, ra); loadB(h + 2, rb); }
        }
        __half* Asm = (__half*)(buf + cur * 16384);
        __half* Bsm = (__half*)(buf + 32768 + cur * 8192);

        #pragma unroll
        for (int ks = 0; ks < 4; ks++) {
            uint32_t a[2][4];
            #pragma unroll
            for (int mt = 0; mt < 2; mt++) {
                int row = wm + (mt << 4) + (lane & 15);
                int chunk = (ks << 1) + (lane >> 4);
                uint32_t addr = (uint32_t)__cvta_generic_to_shared(
                    Asm + row * 64 + ((chunk ^ (row & 7)) << 3));
                asm volatile("ldmatrix.sync.aligned.m8n8.x4.shared.b16 {%0,%1,%2,%3}, [%4];"
                             : "=r"(a[mt][0]), "=r"(a[mt][1]), "=r"(a[mt][2]), "=r"(a[mt][3])
                             : "r"(addr));
            }
            uint32_t b[4][2];
            #pragma unroll
            for (int nt2 = 0; nt2 < 2; nt2++) {
                int krow = (ks << 4) + (lane & 15);
                int nchunk = ((wn + (nt2 << 4)) >> 3) + (lane >> 4);
                uint32_t addr = (uint32_t)__cvta_generic_to_shared(
                    Bsm + krow * 64 + ((nchunk ^ (krow & 7)) << 3));
                uint32_t r0, r1, r2, r3;
                asm volatile("ldmatrix.sync.aligned.m8n8.x4.trans.shared.b16 {%0,%1,%2,%3}, [%4];"
                             : "=r"(r0), "=r"(r1), "=r"(r2), "=r"(r3)
                             : "r"(addr));
                b[nt2 * 2 + 0][0] = r0; b[nt2 * 2 + 0][1] = r1;
                b[nt2 * 2 + 1][0] = r2; b[nt2 * 2 + 1][1] = r3;
            }
            #pragma unroll
            for (int mt = 0; mt < 2; mt++)
                #pragma unroll
                for (int nt = 0; nt < 4; nt++)
                    asm volatile(
                        "mma.sync.aligned.m16n8k16.row.col.f32.f16.f16.f32 "
                        "{%0,%1,%2,%3},{%4,%5,%6,%7},{%8,%9},{%0,%1,%2,%3};"
                        : "+f"(c[mt][nt][0]), "+f"(c[mt][nt][1]),
                          "+f"(c[mt][nt][2]), "+f"(c[mt][nt][3])
                        : "r"(a[mt][0]), "r"(a[mt][1]), "r"(a[mt][2]), "r"(a[mt][3]),
                          "r"(b[nt][0]), "r"(b[nt][1]));
        }
        __syncthreads();
    }

    // epilogue: stage C to smem (Cs aliases the buffers; all reads done)
    int rg = lane >> 2, cg = (lane & 3) << 1;
    #pragma unroll
    for (int mt = 0; mt < 2; mt++) {
        int r = wm + (mt << 4) + rg;
        #pragma unroll
        for (int nt = 0; nt < 4; nt++) {
            int col = wn + (nt << 3) + cg;
            Cs[r * 68 + col]       = c[mt][nt][0];
            Cs[r * 68 + col + 1]   = c[mt][nt][1];
            Cs[(r + 8) * 68 + col]     = c[mt][nt][2];
            Cs[(r + 8) * 68 + col + 1] = c[mt][nt][3];
        }
    }
    __syncthreads();

    float2 gbv = *(const float2*)(gat_b + layer * HID + 2 * lane);
    float2 ggv = *(const float2*)(ln_g  + layer * HID + 2 * lane);
    float2 lbv = *(const float2*)(ln_b  + layer * HID + 2 * lane);
    for (int rr = 0; rr < 16; rr++) {
        int r = wid * 16 + rr;
        int n = m0 + r;
        if (n >= NN) break;
        float v0 = Cs[r * 68 + 2 * lane]     + gbv.x;
        float v1 = Cs[r * 68 + 2 * lane + 1] + gbv.y;
        float sum = v0 + v1, sq = v0 * v0 + v1 * v1;
        #pragma unroll
        for (int s = 16; s > 0; s >>= 1) {
            sum += __shfl_xor_sync(0xFFFFFFFFu, sum, s);
            sq  += __shfl_xor_sync(0xFFFFFFFFu, sq, s);
        }
        float mu   = sum * (1.f / 64.f);
        float var  = sq * (1.f / 64.f) - mu * mu;
        float rstd = rsqrtf(var + 1e-5f);
        v0 = (v0 - mu) * rstd * ggv.x + lbv.x;
        v1 = (v1 - mu) * rstd * ggv.y + lbv.y;
        v0 = v0 > 0.f ? v0 : expm1f(v0);
        v1 = v1 > 0.f ? v1 : expm1f(v1);
        float* hp = g_h + (size_t)n * HID + 2 * lane;
        if (layer > 0) {
            float2 rv = *(const float2*)hp;
            v0 += rv.x; v1 += rv.y;
        }
        Cs[r * 68 + 2 * lane]     = v0;
        Cs[r * 68 + 2 * lane + 1] = v1;
        *(float2*)hp = make_float2(v0, v1);
        *(__half2*)(g_hh + (size_t)n * HID + 2 * lane) = __floats2half2_rn(v0, v1);
    }

    if (do_alpha) {
        __syncthreads();
        int r = t >> 1, hs = t & 1;
        int n = m0 + r;
        if (n < NN) {
            const float* wv = wa_sm + hs * 4 * 64;
            float a0 = 0.f, a1 = 0.f, a2 = 0.f, a3 = 0.f;
            #pragma unroll
            for (int cc = 0; cc < 64; cc++) {
                float hv = Cs[r * 68 + cc];
                a0 += hv * wv[cc];
                a1 += hv * wv[64 + cc];
                a2 += hv * wv[128 + cc];
                a3 += hv * wv[192 + cc];
            }
            float* dst = (hs == 0 ? g_as : g_ad) + 4 * (size_t)n;
            *(float4*)dst = make_float4(a0, a1, a2, a3);
        }
    }

    if (last) {
        __half* Asm2 = (__half*)(buf + 36864);
        __half* Bsm2 = (__half*)(buf + 53248);
        __syncthreads();
        #pragma unroll
        for (int i = 0; i < 4; i++) {
            int cid = t + i * 256;
            int r = cid >> 3, cc = cid & 7;
            const float* src = Cs + r * 68 + (cc << 3);
            __half2 hv[4];
            hv[0] = __floats2half2_rn(src[0], src[1]);
            hv[1] = __floats2half2_rn(src[2], src[3]);
            hv[2] = __floats2half2_rn(src[4], src[5]);
            hv[3] = __floats2half2_rn(src[6], src[7]);
            *(uint4*)(Asm2 + r * 64 + ((cc ^ (r & 7)) << 3)) = *(uint4*)hv;
        }
        #pragma unroll
        for (int i = 0; i < 2; i++) {
            int cid = t + i * 256;
            int k = cid >> 3, cc = cid & 7;
            uint4 v = *(const uint4*)(g_woh + k * 64 + (cc << 3));
            *(uint4*)(Bsm2 + k * 64 + ((cc ^ (k & 7)) << 3)) = v;
        }
        __syncthreads();

        float co[2][4][4] = {};
        #pragma unroll
        for (int ks = 0; ks < 4; ks++) {
            uint32_t a[2][4];
            #pragma unroll
            for (int mt = 0; mt < 2; mt++) {
                int row = wm + (mt << 4) + (lane & 15);
                int chunk = (ks << 1) + (lane >> 4);
                uint32_t addr = (uint32_t)__cvta_generic_to_shared(
                    Asm2 + row * 64 + ((chunk ^ (row & 7)) << 3));
                asm volatile("ldmatrix.sync.aligned.m8n8.x4.shared.b16 {%0,%1,%2,%3}, [%4];"
                             : "=r"(a[mt][0]), "=r"(a[mt][1]), "=r"(a[mt][2]), "=r"(a[mt][3])
                             : "r"(addr));
            }
            uint32_t b[4][2];
            #pragma unroll
            for (int nt2 = 0; nt2 < 2; nt2++) {
                int krow = (ks << 4) + (lane & 15);
                int nchunk = ((wn + (nt2 << 4)) >> 3) + (lane >> 4);
                uint32_t addr = (uint32_t)__cvta_generic_to_shared(
                    Bsm2 + krow * 64 + ((nchunk ^ (krow & 7)) << 3));
                uint32_t r0, r1, r2, r3;
                asm volatile("ldmatrix.sync.aligned.m8n8.x4.trans.shared.b16 {%0,%1,%2,%3}, [%4];"
                             : "=r"(r0), "=r"(r1), "=r"(r2), "=r"(r3)
                             : "r"(addr));
                b[nt2 * 2 + 0][0] = r0; b[nt2 * 2 + 0][1] = r1;
                b[nt2 * 2 + 1][0] = r2; b[nt2 * 2 + 1][1] = r3;
            }
            #pragma unroll
            for (int mt = 0; mt < 2; mt++)
                #pragma unroll
                for (int nt = 0; nt < 4; nt++)
                    asm volatile(
                        "mma.sync.aligned.m16n8k16.row.col.f32.f16.f16.f32 "
                        "{%0,%1,%2,%3},{%4,%5,%6,%7},{%8,%9},{%0,%1,%2,%3};"
                        : "+f"(co[mt][nt][0]), "+f"(co[mt][nt][1]),
                          "+f"(co[mt][nt][2]), "+f"(co[mt][nt][3])
                        : "r"(a[mt][0]), "r"(a[mt][1]), "r"(a[mt][2]), "r"(a[mt][3]),
                          "r"(b[nt][0]), "r"(b[nt][1]));
        }

        #pragma unroll
        for (int nt = 0; nt < 4; nt++) {
            int col = wn + (nt << 3) + cg;
            if (col >= OUTC) continue;
            float b0 = bo[col], b1 = bo[col + 1];
            #pragma unroll
            for (int mt = 0; mt < 2; mt++) {
                #pragma unroll
                for (int half_ = 0; half_ < 2; half_++) {
                    int r = m0 + wm + (mt << 4) + rg + half_ * 8;
                    if (r >= NN) continue;
                    *(float2*)(out + (size_t)r * OUTC + col) =
                        make_float2(co[mt][nt][half_ * 2 + 0] + b0,
                                    co[mt][nt][half_ * 2 + 1] + b1);
                }
            }
        }
    }
}

// ---------------- host orchestration ----------------
extern "C" void kernel_launch(void* const* d_in, const int* in_sizes, int n_in,
                              void* d_out, int out_size) {
    const float* x       = (const float*)d_in[0];
    const int*   ei      = (const int*)d_in[1];
    const float* Wi      = (const float*)d_in[2];
    const float* bi      = (const float*)d_in[3];
    const float* lin_W   = (const float*)d_in[4];
    const float* att_src = (const float*)d_in[5];
    const float* att_dst = (const float*)d_in[6];
    const float* gat_b   = (const float*)d_in[7];
    const float* ln_g    = (const float*)d_in[8];
    const float* ln_b    = (const float*)d_in[9];
    const float* Wo      = (const float*)d_in[10];
    const float* bo      = (const float*)d_in[11];
    float* out = (float*)d_out;

    static bool inited = false;
    static cudaStream_t s1;
    static cudaEvent_t ev0, ev1;
    if (!inited) {
        cudaStreamCreateWithFlags(&s1, cudaStreamNonBlocking);
        cudaEventCreateWithFlags(&ev0, cudaEventDisableTiming);
        cudaEventCreateWithFlags(&ev1, cudaEventDisableTiming);
        cudaFuncSetAttribute(gemm_agg, cudaFuncAttributeMaxDynamicSharedMemorySize, 61440);
        inited = true;
    }

    const int EB4 = (ETOT + 1023) / 1024;
    const int MB  = (NN + 127) / 128;

    // ---- fork: CSR chain on side stream ----
    cudaEventRecord(ev0, 0);
    cudaStreamWaitEvent(s1, ev0, 0);
    hist_kernel<<<EB4, 256, 0, s1>>>(ei);
    scan1_kernel<<<SB, 1024, 0, s1>>>();
    scan3_kernel<<<SB, 1024, 0, s1>>>();
    scatter_kernel<<<EB4, 256, 0, s1>>>(ei);
    cudaEventRecord(ev1, s1);

    // ---- main stream ----
    prep_kernel<<<40 + 256, 256>>>(Wi, Wo, lin_W, att_src, att_dst);
    gemm_in<<<MB, 256>>>(x, bi);

    cudaStreamWaitEvent(0, ev1, 0);

    for (int l = 0; l < NLAY; l++) {
        int last = (l == NLAY - 1);
        agg_h_kernel<<<(NN + 7) / 8, 256>>>();
        gemm_agg<<<MB, 256, last ? 61440 : 51200>>>(gat_b, ln_g, ln_b, l, bo, out, last);
    }
}

// round 16
// speedup vs baseline: 1.1081x; 1.1081x over previous
#include <cuda_runtime.h>
#include <cuda_fp16.h>
#include <cmath>
#include <cstdint>

#define NN   50000
#define EE   800000
#define ETOT 850000
#define INC  128
#define HID  64
#define NH   4
#define HK   256
#define OUTC 40
#define NLAY 4
#define SB   13

// ---------------- device scratch ----------------
__device__ float  g_h[(size_t)NN * HID];
__device__ __half g_hh[(size_t)NN * HID];
__device__ __half g_agg[(size_t)NN * HK];
__device__ float  g_as[(size_t)NN * NH];
__device__ float  g_ad[(size_t)NN * NH];
__device__ float  g_wa[NLAY * 8 * HID];
__device__ __half g_wc[NLAY * NH * HID * HID];
__device__ __half g_wih[INC * HID];
__device__ __half g_woh[HID * 64];
__device__ int    g_deg[NN];          // zero at module load; scan1 re-zeroes each launch
__device__ int    g_rowptr[NN + 1];
__device__ int    g_erank[ETOT];
__device__ int    g_csrc[ETOT];
__device__ int    g_bsum[16];

// ---------------- CSR build ----------------
__global__ void hist_kernel(const int* __restrict__ ei) {
    int e0 = (blockIdx.x * blockDim.x + threadIdx.x) * 4;
    if (e0 >= ETOT) return;
    if (e0 < EE) {
        int4 d4 = *(const int4*)(ei + EE + e0);
        int4 r4;
        r4.x = atomicAdd(&g_deg[d4.x], 1);
        r4.y = atomicAdd(&g_deg[d4.y], 1);
        r4.z = atomicAdd(&g_deg[d4.z], 1);
        r4.w = atomicAdd(&g_deg[d4.w], 1);
        __stcs((int4*)(g_erank + e0), r4);
    } else {
        #pragma unroll
        for (int k = 0; k < 4; k++) {
            int e = e0 + k;
            if (e >= ETOT) return;
            g_erank[e] = atomicAdd(&g_deg[e - EE], 1);
        }
    }
}

__global__ void scan1_kernel() {
    __shared__ int wsum[32];
    int t = threadIdx.x;
    int i0 = blockIdx.x * 4096 + t * 4;
    int4 v = make_int4(0, 0, 0, 0);
    if (i0 + 3 < NN) {
        v = *(const int4*)(g_deg + i0);
        *(int4*)(g_deg + i0) = make_int4(0, 0, 0, 0);
    } else {
        if (i0 + 0 < NN) { v.x = g_deg[i0 + 0]; g_deg[i0 + 0] = 0; }
        if (i0 + 1 < NN) { v.y = g_deg[i0 + 1]; g_deg[i0 + 1] = 0; }
        if (i0 + 2 < NN) { v.z = g_deg[i0 + 2]; g_deg[i0 + 2] = 0; }
        if (i0 + 3 < NN) { v.w = g_deg[i0 + 3]; g_deg[i0 + 3] = 0; }
    }
    int tot = v.x + v.y + v.z + v.w;
    int x = tot;
    #pragma unroll
    for (int s = 1; s < 32; s <<= 1) {
        int y = __shfl_up_sync(0xFFFFFFFFu, x, s);
        if ((t & 31) >= s) x += y;
    }
    if ((t & 31) == 31) wsum[t >> 5] = x;
    __syncthreads();
    if (t < 32) {
        int y = wsum[t];
        #pragma unroll
        for (int s = 1; s < 32; s <<= 1) {
            int z = __shfl_up_sync(0xFFFFFFFFu, y, s);
            if (t >= s) y += z;
        }
        wsum[t] = y;
    }
    __syncthreads();
    int excl = x - tot + ((t >= 32) ? wsum[(t >> 5) - 1] : 0);
    if (i0 + 3 < NN) {
        *(int4*)(g_rowptr + i0) =
            make_int4(excl, excl + v.x, excl + v.x + v.y, excl + v.x + v.y + v.z);
    } else {
        if (i0 + 0 < NN) g_rowptr[i0 + 0] = excl;
        if (i0 + 1 < NN) g_rowptr[i0 + 1] = excl + v.x;
        if (i0 + 2 < NN) g_rowptr[i0 + 2] = excl + v.x + v.y;
        if (i0 + 3 < NN) g_rowptr[i0 + 3] = excl + v.x + v.y + v.z;
    }
    if (t == 0) g_bsum[blockIdx.x] = wsum[31];
}

__global__ void scan3_kernel() {
    __shared__ int offs[SB];
    __shared__ int tot_sh;
    int t = threadIdx.x;
    if (t < 32) {
        int v = (t < SB) ? g_bsum[t] : 0;
        int x = v;
        #pragma unroll
        for (int s = 1; s < 32; s <<= 1) {
            int y = __shfl_up_sync(0xFFFFFFFFu, x, s);
            if (t >= s) x += y;
        }
        if (t < SB) offs[t] = x - v;
        if (t == 31) tot_sh = x;
    }
    __syncthreads();
    int off = offs[blockIdx.x];
    int i0 = blockIdx.x * 4096 + t * 4;
    if (i0 + 3 < NN) {
        int4 r = *(const int4*)(g_rowptr + i0);
        r.x += off; r.y += off; r.z += off; r.w += off;
        *(int4*)(g_rowptr + i0) = r;
    } else {
        for (int k = 0; k < 4; k++) {
            if (i0 + k < NN) g_rowptr[i0 + k] += off;
        }
    }
    if (blockIdx.x == 0 && t == 0) g_rowptr[NN] = tot_sh;
}

// scatter: atomic-free — position = rowptr[dst] + rank; streaming hints
__global__ void scatter_kernel(const int* __restrict__ ei) {
    int e0 = (blockIdx.x * blockDim.x + threadIdx.x) * 4;
    if (e0 >= ETOT) return;
    if (e0 < EE) {
        int4 s4 = __ldcs((const int4*)(ei + e0));
        int4 d4 = __ldcs((const int4*)(ei + EE + e0));
        int4 r4 = __ldcs((const int4*)(g_erank + e0));
        __stcs(g_csrc + g_rowptr[d4.x] + r4.x, s4.x);
        __stcs(g_csrc + g_rowptr[d4.y] + r4.y, s4.y);
        __stcs(g_csrc + g_rowptr[d4.z] + r4.z, s4.z);
        __stcs(g_csrc + g_rowptr[d4.w] + r4.w, s4.w);
    } else {
        #pragma unroll
        for (int k = 0; k < 4; k++) {
            int e = e0 + k;
            if (e >= ETOT) return;
            int n = e - EE;
            __stcs(g_csrc + g_rowptr[n] + g_erank[e], n);
        }
    }
}

// ---------------- fused prep ----------------
__global__ void prep_kernel(const float* __restrict__ Wi,
                            const float* __restrict__ Wo,
                            const float* __restrict__ lin_W,
                            const float* __restrict__ att_src,
                            const float* __restrict__ att_dst) {
    int b = blockIdx.x, t = threadIdx.x;
    if (b < 32) {
        int i = b * 256 + t;
        if (i < INC * HID) g_wih[i] = __float2half(Wi[i]);
        if (i < HID * 64) {
            int k = i >> 6, c = i & 63;
            g_woh[i] = __float2half(c < OUTC ? Wo[k * OUTC + c] : 0.f);
        }
    } else if (b < 40) {
        int tid = (b - 32) * 256 + t;
        if (tid >= NLAY * 8 * HID) return;
        int k = tid & 63;
        int v = (tid >> 6) & 7;
        int l = tid >> 9;
        int h = v & 3;
        const float* att  = (v < 4) ? att_src : att_dst;
        const float* wrow = lin_W + (size_t)l * HID * HK + (size_t)k * HK + h * HID;
        const float* arow = att + l * HK + h * HID;
        float s = 0.f;
        #pragma unroll
        for (int c = 0; c < HID; c++) s += wrow[c] * arow[c];
        g_wa[tid] = s;
    } else {
        int tid = (b - 40) * 256 + t;
        if (tid >= NLAY * NH * HID * HID) return;
        int c = tid & 63;
        int k = (tid >> 6) & 63;
        int h = (tid >> 12) & 3;
        int l = tid >> 14;
        g_wc[tid] = __float2half(0.25f * lin_W[(size_t)l * HID * HK + (size_t)k * HK + h * HID + c]);
    }
}

// ---------------- MMA input GEMM (reads fp32 x directly) + fused layer-0 alpha ----------------
__global__ void gemm_in(const float* __restrict__ x, const float* __restrict__ bi) {
    __shared__ alignas(16) char buf[49152];
    __half* Asm = (__half*)buf;
    __half* Bsm = (__half*)(buf + 32768);
    float*  Cs  = (float*)buf;
    float*  wa_sm = (float*)(buf + 47104);

    int t = threadIdx.x;
    int m0 = blockIdx.x << 7;
    #pragma unroll
    for (int i = 0; i < 8; i++) {
        int cid = t + i * 256;
        int r = cid >> 4, c = cid & 15;
        __half2 hv[4] = {};
        if (m0 + r < NN) {
            const float* src = x + (size_t)(m0 + r) * INC + (c << 3);
            float4 f0 = *(const float4*)src;
            float4 f1 = *(const float4*)(src + 4);
            hv[0] = __floats2half2_rn(f0.x, f0.y);
            hv[1] = __floats2half2_rn(f0.z, f0.w);
            hv[2] = __floats2half2_rn(f1.x, f1.y);
            hv[3] = __floats2half2_rn(f1.z, f1.w);
        }
        *(uint4*)(Asm + r * 128 + ((c ^ (r & 7)) << 3)) = *(uint4*)hv;
    }
    #pragma unroll
    for (int i = 0; i < 4; i++) {
        int cid = t + i * 256;
        int k = cid >> 3, c = cid & 7;
        uint4 v = *(const uint4*)(g_wih + k * 64 + (c << 3));
        *(uint4*)(Bsm + k * 64 + ((c ^ (k & 7)) << 3)) = v;
    }
    __syncthreads();

    int wid = t >> 5, lane = t & 31;
    int wm = (wid & 3) << 5;
    int wn = (wid >> 2) << 5;
    float c[2][4][4] = {};

    #pragma unroll
    for (int ks = 0; ks < 8; ks++) {
        uint32_t a[2][4];
        #pragma unroll
        for (int mt = 0; mt < 2; mt++) {
            int row = wm + (mt << 4) + (lane & 15);
            int chunk = (ks << 1) + (lane >> 4);
            uint32_t addr = (uint32_t)__cvta_generic_to_shared(
                Asm + row * 128 + ((chunk ^ (row & 7)) << 3));
            asm volatile("ldmatrix.sync.aligned.m8n8.x4.shared.b16 {%0,%1,%2,%3}, [%4];"
                         : "=r"(a[mt][0]), "=r"(a[mt][1]), "=r"(a[mt][2]), "=r"(a[mt][3])
                         : "r"(addr));
        }
        uint32_t b[4][2];
        #pragma unroll
        for (int nt2 = 0; nt2 < 2; nt2++) {
            int krow = (ks << 4) + (lane & 15);
            int nchunk = ((wn + (nt2 << 4)) >> 3) + (lane >> 4);
            uint32_t addr = (uint32_t)__cvta_generic_to_shared(
                Bsm + krow * 64 + ((nchunk ^ (krow & 7)) << 3));
            uint32_t r0, r1, r2, r3;
            asm volatile("ldmatrix.sync.aligned.m8n8.x4.trans.shared.b16 {%0,%1,%2,%3}, [%4];"
                         : "=r"(r0), "=r"(r1), "=r"(r2), "=r"(r3)
                         : "r"(addr));
            b[nt2 * 2 + 0][0] = r0; b[nt2 * 2 + 0][1] = r1;
            b[nt2 * 2 + 1][0] = r2; b[nt2 * 2 + 1][1] = r3;
        }
        #pragma unroll
        for (int mt = 0; mt < 2; mt++)
            #pragma unroll
            for (int nt = 0; nt < 4; nt++)
                asm volatile(
                    "mma.sync.aligned.m16n8k16.row.col.f32.f16.f16.f32 "
                    "{%0,%1,%2,%3},{%4,%5,%6,%7},{%8,%9},{%0,%1,%2,%3};"
                    : "+f"(c[mt][nt][0]), "+f"(c[mt][nt][1]),
                      "+f"(c[mt][nt][2]), "+f"(c[mt][nt][3])
                    : "r"(a[mt][0]), "r"(a[mt][1]), "r"(a[mt][2]), "r"(a[mt][3]),
                      "r"(b[nt][0]), "r"(b[nt][1]));
    }

    __syncthreads();
    #pragma unroll
    for (int i = 0; i < 2; i++)
        wa_sm[t + i * 256] = g_wa[t + i * 256];

    int rg = lane >> 2, cg = (lane & 3) << 1;
    #pragma unroll
    for (int nt = 0; nt < 4; nt++) {
        int col = wn + (nt << 3) + cg;
        float b0 = bi[col], b1 = bi[col + 1];
        #pragma unroll
        for (int mt = 0; mt < 2; mt++) {
            #pragma unroll
            for (int half_ = 0; half_ < 2; half_++) {
                int rl = wm + (mt << 4) + rg + half_ * 8;
                int r = m0 + rl;
                float v0 = c[mt][nt][half_ * 2 + 0] + b0;
                float v1 = c[mt][nt][half_ * 2 + 1] + b1;
                v0 = v0 > 0.f ? v0 : expm1f(v0);
                v1 = v1 > 0.f ? v1 : expm1f(v1);
                Cs[rl * 68 + col]     = v0;
                Cs[rl * 68 + col + 1] = v1;
                if (r < NN) {
                    *(float2*)(g_h + (size_t)r * HID + col) = make_float2(v0, v1);
                    *(__half2*)(g_hh + (size_t)r * HID + col) = __floats2half2_rn(v0, v1);
                }
            }
        }
    }
    __syncthreads();

    {
        int r = t >> 1, hs = t & 1;
        int n = m0 + r;
        if (n < NN) {
            const float* wv = wa_sm + hs * 4 * 64;
            float a0 = 0.f, a1 = 0.f, a2 = 0.f, a3 = 0.f;
            #pragma unroll
            for (int cc = 0; cc < 64; cc++) {
                float hv = Cs[r * 68 + cc];
                a0 += hv * wv[cc];
                a1 += hv * wv[64 + cc];
                a2 += hv * wv[128 + cc];
                a3 += hv * wv[192 + cc];
            }
            float* dst = (hs == 0 ? g_as : g_ad) + 4 * (size_t)n;
            *(float4*)dst = make_float4(a0, a1, a2, a3);
        }
    }
}

// ---------------- aggregation in h-space (R6 exact) ----------------
__global__ void agg_h_kernel() {
    __shared__ float sp[8][32][4];
    int wl   = threadIdx.x >> 5;
    int w    = (blockIdx.x * blockDim.x + threadIdx.x) >> 5;
    int lane = threadIdx.x & 31;
    if (w >= NN) return;

    float4 ad4 = *(const float4*)(g_ad + 4 * (size_t)w);

    float acc[4][2] = {};
    float denl[4] = {};
    int beg = g_rowptr[w], end = g_rowptr[w + 1];

    for (int base = beg; base < end; base += 32) {
        int idx = base + lane;
        bool valid = idx < end;
        int sv = valid ? g_csrc[idx] : 0;
        float4 as4 = *(const float4*)(g_as + 4 * (size_t)sv);
        float p0, p1, p2, p3;
        {
            float e0 = as4.x + ad4.x, e1 = as4.y + ad4.y;
            float e2 = as4.z + ad4.z, e3 = as4.w + ad4.w;
            e0 = e0 > 0.f ? e0 : 0.2f * e0;
            e1 = e1 > 0.f ? e1 : 0.2f * e1;
            e2 = e2 > 0.f ? e2 : 0.2f * e2;
            e3 = e3 > 0.f ? e3 : 0.2f * e3;
            p0 = valid ? __expf(e0) : 0.f;
            p1 = valid ? __expf(e1) : 0.f;
            p2 = valid ? __expf(e2) : 0.f;
            p3 = valid ? __expf(e3) : 0.f;
        }
        denl[0] += p0; denl[1] += p1; denl[2] += p2; denl[3] += p3;
        *(float4*)&sp[wl][lane][0] = make_float4(p0, p1, p2, p3);
        __syncwarp();

        int m = end - base; if (m > 32) m = 32;
        int j = 0;
        for (; j + 1 < m; j += 2) {
            int sA = __shfl_sync(0xFFFFFFFFu, sv, j);
            int sB = __shfl_sync(0xFFFFFFFFu, sv, j + 1);
            float4 pA = *(const float4*)&sp[wl][j][0];
            float4 pB = *(const float4*)&sp[wl][j + 1][0];
            __half2 hA = *(const __half2*)(g_hh + (size_t)sA * HID + 2 * lane);
            __half2 hB = *(const __half2*)(g_hh + (size_t)sB * HID + 2 * lane);
            float2 fA = __half22float2(hA);
            float2 fB = __half22float2(hB);
            acc[0][0] += pA.x * fA.x + pB.x * fB.x;
            acc[0][1] += pA.x * fA.y + pB.x * fB.y;
            acc[1][0] += pA.y * fA.x + pB.y * fB.x;
            acc[1][1] += pA.y * fA.y + pB.y * fB.y;
            acc[2][0] += pA.z * fA.x + pB.z * fB.x;
            acc[2][1] += pA.z * fA.y + pB.z * fB.y;
            acc[3][0] += pA.w * fA.x + pB.w * fB.x;
            acc[3][1] += pA.w * fA.y + pB.w * fB.y;
        }
        if (j < m) {
            int s = __shfl_sync(0xFFFFFFFFu, sv, j);
            float4 pj = *(const float4*)&sp[wl][j][0];
            __half2 hv = *(const __half2*)(g_hh + (size_t)s * HID + 2 * lane);
            float2 f = __half22float2(hv);
            acc[0][0] += pj.x * f.x; acc[0][1] += pj.x * f.y;
            acc[1][0] += pj.y * f.x; acc[1][1] += pj.y * f.y;
            acc[2][0] += pj.z * f.x; acc[2][1] += pj.z * f.y;
            acc[3][0] += pj.w * f.x; acc[3][1] += pj.w * f.y;
        }
        __syncwarp();
    }

    #pragma unroll
    for (int h = 0; h < 4; h++) {
        float d = denl[h];
        #pragma unroll
        for (int s = 16; s > 0; s >>= 1)
            d += __shfl_xor_sync(0xFFFFFFFFu, d, s);
        denl[h] = 1.f / (d + 1e-16f);
    }

    __half* ap = g_agg + (size_t)w * HK;
    #pragma unroll
    for (int h = 0; h < 4; h++) {
        *(__half2*)(ap + h * HID + 2 * lane) =
            __floats2half2_rn(acc[h][0] * denl[h], acc[h][1] * denl[h]);
    }
}

// ---------------- MMA head-mix GEMM + epilogue + next-layer alpha + (last) output GEMM ----------------
__global__ void gemm_agg(const float* __restrict__ gat_b,
                         const float* __restrict__ ln_g,
                         const float* __restrict__ ln_b, int layer,
                         const float* __restrict__ bo, float* __restrict__ out,
                         int last) {
    extern __shared__ char buf[];
    __half* Asm = (__half*)buf;
    __half* Bsm = (__half*)(buf + 16384);
    float*  Cs  = (float*)buf;
    float*  wa_sm = (float*)(buf + 34816);

    int t  = threadIdx.x;
    int m0 = blockIdx.x << 7;
    int wid = t >> 5, lane = t & 31;
    int wm = (wid & 3) << 5;
    int wn = (wid >> 2) << 5;
    bool do_alpha = (layer + 1 < NLAY);

    if (do_alpha) {
        #pragma unroll
        for (int i = 0; i < 2; i++)
            wa_sm[t + i * 256] = g_wa[(layer + 1) * 512 + t + i * 256];
    }

    float c[2][4][4] = {};

    for (int h = 0; h < 4; h++) {
        if (h) __syncthreads();
        #pragma unroll
        for (int i = 0; i < 4; i++) {
            int cid = t + i * 256;
            int r = cid >> 3, cc = cid & 7;
            uint4 v = make_uint4(0, 0, 0, 0);
            if (m0 + r < NN)
                v = *(const uint4*)(g_agg + (size_t)(m0 + r) * HK + h * HID + (cc << 3));
            *(uint4*)(Asm + r * 64 + ((cc ^ (r & 7)) << 3)) = v;
        }
        const __half* wb = g_wc + (size_t)(layer * 4 + h) * HID * HID;
        #pragma unroll
        for (int i = 0; i < 2; i++) {
            int cid = t + i * 256;
            int k = cid >> 3, cc = cid & 7;
            uint4 v = *(const uint4*)(wb + k * 64 + (cc << 3));
            *(uint4*)(Bsm + k * 64 + ((cc ^ (k & 7)) << 3)) = v;
        }
        __syncthreads();

        #pragma unroll
        for (int ks = 0; ks < 4; ks++) {
            uint32_t a[2][4];
            #pragma unroll
            for (int mt = 0; mt < 2; mt++) {
                int row = wm + (mt << 4) + (lane & 15);
                int chunk = (ks << 1) + (lane >> 4);
                uint32_t addr = (uint32_t)__cvta_generic_to_shared(
                    Asm + row * 64 + ((chunk ^ (row & 7)) << 3));
                asm volatile("ldmatrix.sync.aligned.m8n8.x4.shared.b16 {%0,%1,%2,%3}, [%4];"
                             : "=r"(a[mt][0]), "=r"(a[mt][1]), "=r"(a[mt][2]), "=r"(a[mt][3])
                             : "r"(addr));
            }
            uint32_t b[4][2];
            #pragma unroll
            for (int nt2 = 0; nt2 < 2; nt2++) {
                int krow = (ks << 4) + (lane & 15);
                int nchunk = ((wn + (nt2 << 4)) >> 3) + (lane >> 4);
                uint32_t addr = (uint32_t)__cvta_generic_to_shared(
                    Bsm + krow * 64 + ((nchunk ^ (krow & 7)) << 3));
                uint32_t r0, r1, r2, r3;
                asm volatile("ldmatrix.sync.aligned.m8n8.x4.trans.shared.b16 {%0,%1,%2,%3}, [%4];"
                             : "=r"(r0), "=r"(r1), "=r"(r2), "=r"(r3)
                             : "r"(addr));
                b[nt2 * 2 + 0][0] = r0; b[nt2 * 2 + 0][1] = r1;
                b[nt2 * 2 + 1][0] = r2; b[nt2 * 2 + 1][1] = r3;
            }
            #pragma unroll
            for (int mt = 0; mt < 2; mt++)
                #pragma unroll
                for (int nt = 0; nt < 4; nt++)
                    asm volatile(
                        "mma.sync.aligned.m16n8k16.row.col.f32.f16.f16.f32 "
                        "{%0,%1,%2,%3},{%4,%5,%6,%7},{%8,%9},{%0,%1,%2,%3};"
                        : "+f"(c[mt][nt][0]), "+f"(c[mt][nt][1]),
                          "+f"(c[mt][nt][2]), "+f"(c[mt][nt][3])
                        : "r"(a[mt][0]), "r"(a[mt][1]), "r"(a[mt][2]), "r"(a[mt][3]),
                          "r"(b[nt][0]), "r"(b[nt][1]));
        }
    }

    __syncthreads();
    int rg = lane >> 2, cg = (lane & 3) << 1;
    #pragma unroll
    for (int mt = 0; mt < 2; mt++) {
        int r = wm + (mt << 4) + rg;
        #pragma unroll
        for (int nt = 0; nt < 4; nt++) {
            int col = wn + (nt << 3) + cg;
            Cs[r * 68 + col]       = c[mt][nt][0];
            Cs[r * 68 + col + 1]   = c[mt][nt][1];
            Cs[(r + 8) * 68 + col]     = c[mt][nt][2];
            Cs[(r + 8) * 68 + col + 1] = c[mt][nt][3];
        }
    }
    __syncthreads();

    float2 gbv = *(const float2*)(gat_b + layer * HID + 2 * lane);
    float2 ggv = *(const float2*)(ln_g  + layer * HID + 2 * lane);
    float2 lbv = *(const float2*)(ln_b  + layer * HID + 2 * lane);
    for (int rr = 0; rr < 16; rr++) {
        int r = wid * 16 + rr;
        int n = m0 + r;
        if (n >= NN) break;
        float v0 = Cs[r * 68 + 2 * lane]     + gbv.x;
        float v1 = Cs[r * 68 + 2 * lane + 1] + gbv.y;
        float sum = v0 + v1, sq = v0 * v0 + v1 * v1;
        #pragma unroll
        for (int s = 16; s > 0; s >>= 1) {
            sum += __shfl_xor_sync(0xFFFFFFFFu, sum, s);
            sq  += __shfl_xor_sync(0xFFFFFFFFu, sq, s);
        }
        float mu   = sum * (1.f / 64.f);
        float var  = sq * (1.f / 64.f) - mu * mu;
        float rstd = rsqrtf(var + 1e-5f);
        v0 = (v0 - mu) * rstd * ggv.x + lbv.x;
        v1 = (v1 - mu) * rstd * ggv.y + lbv.y;
        v0 = v0 > 0.f ? v0 : expm1f(v0);
        v1 = v1 > 0.f ? v1 : expm1f(v1);
        float* hp = g_h + (size_t)n * HID + 2 * lane;
        if (layer > 0) {
            float2 rv = *(const float2*)hp;
            v0 += rv.x; v1 += rv.y;
        }
        Cs[r * 68 + 2 * lane]     = v0;
        Cs[r * 68 + 2 * lane + 1] = v1;
        *(float2*)hp = make_float2(v0, v1);
        *(__half2*)(g_hh + (size_t)n * HID + 2 * lane) = __floats2half2_rn(v0, v1);
    }

    if (do_alpha) {
        __syncthreads();
        int r = t >> 1, hs = t & 1;
        int n = m0 + r;
        if (n < NN) {
            const float* wv = wa_sm + hs * 4 * 64;
            float a0 = 0.f, a1 = 0.f, a2 = 0.f, a3 = 0.f;
            #pragma unroll
            for (int cc = 0; cc < 64; cc++) {
                float hv = Cs[r * 68 + cc];
                a0 += hv * wv[cc];
                a1 += hv * wv[64 + cc];
                a2 += hv * wv[128 + cc];
                a3 += hv * wv[192 + cc];
            }
            float* dst = (hs == 0 ? g_as : g_ad) + 4 * (size_t)n;
            *(float4*)dst = make_float4(a0, a1, a2, a3);
        }
    }

    if (last) {
        __half* Asm2 = (__half*)(buf + 36864);
        __half* Bsm2 = (__half*)(buf + 53248);
        __syncthreads();
        #pragma unroll
        for (int i = 0; i < 4; i++) {
            int cid = t + i * 256;
            int r = cid >> 3, cc = cid & 7;
            const float* src = Cs + r * 68 + (cc << 3);
            __half2 hv[4];
            hv[0] = __floats2half2_rn(src[0], src[1]);
            hv[1] = __floats2half2_rn(src[2], src[3]);
            hv[2] = __floats2half2_rn(src[4], src[5]);
            hv[3] = __floats2half2_rn(src[6], src[7]);
            *(uint4*)(Asm2 + r * 64 + ((cc ^ (r & 7)) << 3)) = *(uint4*)hv;
        }
        #pragma unroll
        for (int i = 0; i < 2; i++) {
            int cid = t + i * 256;
            int k = cid >> 3, cc = cid & 7;
            uint4 v = *(const uint4*)(g_woh + k * 64 + (cc << 3));
            *(uint4*)(Bsm2 + k * 64 + ((cc ^ (k & 7)) << 3)) = v;
        }
        __syncthreads();

        float co[2][4][4] = {};
        #pragma unroll
        for (int ks = 0; ks < 4; ks++) {
            uint32_t a[2][4];
            #pragma unroll
            for (int mt = 0; mt < 2; mt++) {
                int row = wm + (mt << 4) + (lane & 15);
                int chunk = (ks << 1) + (lane >> 4);
                uint32_t addr = (uint32_t)__cvta_generic_to_shared(
                    Asm2 + row * 64 + ((chunk ^ (row & 7)) << 3));
                asm volatile("ldmatrix.sync.aligned.m8n8.x4.shared.b16 {%0,%1,%2,%3}, [%4];"
                             : "=r"(a[mt][0]), "=r"(a[mt][1]), "=r"(a[mt][2]), "=r"(a[mt][3])
                             : "r"(addr));
            }
            uint32_t b[4][2];
            #pragma unroll
            for (int nt2 = 0; nt2 < 2; nt2++) {
                int krow = (ks << 4) + (lane & 15);
                int nchunk = ((wn + (nt2 << 4)) >> 3) + (lane >> 4);
                uint32_t addr = (uint32_t)__cvta_generic_to_shared(
                    Bsm2 + krow * 64 + ((nchunk ^ (krow & 7)) << 3));
                uint32_t r0, r1, r2, r3;
                asm volatile("ldmatrix.sync.aligned.m8n8.x4.trans.shared.b16 {%0,%1,%2,%3}, [%4];"
                             : "=r"(r0), "=r"(r1), "=r"(r2), "=r"(r3)
                             : "r"(addr));
                b[nt2 * 2 + 0][0] = r0; b[nt2 * 2 + 0][1] = r1;
                b[nt2 * 2 + 1][0] = r2; b[nt2 * 2 + 1][1] = r3;
            }
            #pragma unroll
            for (int mt = 0; mt < 2; mt++)
                #pragma unroll
                for (int nt = 0; nt < 4; nt++)
                    asm volatile(
                        "mma.sync.aligned.m16n8k16.row.col.f32.f16.f16.f32 "
                        "{%0,%1,%2,%3},{%4,%5,%6,%7},{%8,%9},{%0,%1,%2,%3};"
                        : "+f"(co[mt][nt][0]), "+f"(co[mt][nt][1]),
                          "+f"(co[mt][nt][2]), "+f"(co[mt][nt][3])
                        : "r"(a[mt][0]), "r"(a[mt][1]), "r"(a[mt][2]), "r"(a[mt][3]),
                          "r"(b[nt][0]), "r"(b[nt][1]));
        }

        #pragma unroll
        for (int nt = 0; nt < 4; nt++) {
            int col = wn + (nt << 3) + cg;
            if (col >= OUTC) continue;
            float b0 = bo[col], b1 = bo[col + 1];
            #pragma unroll
            for (int mt = 0; mt < 2; mt++) {
                #pragma unroll
                for (int half_ = 0; half_ < 2; half_++) {
                    int r = m0 + wm + (mt << 4) + rg + half_ * 8;
                    if (r >= NN) continue;
                    *(float2*)(out + (size_t)r * OUTC + col) =
                        make_float2(co[mt][nt][half_ * 2 + 0] + b0,
                                    co[mt][nt][half_ * 2 + 1] + b1);
                }
            }
        }
    }
}

// ---------------- host orchestration ----------------
extern "C" void kernel_launch(void* const* d_in, const int* in_sizes, int n_in,
                              void* d_out, int out_size) {
    const float* x       = (const float*)d_in[0];
    const int*   ei      = (const int*)d_in[1];
    const float* Wi      = (const float*)d_in[2];
    const float* bi      = (const float*)d_in[3];
    const float* lin_W   = (const float*)d_in[4];
    const float* att_src = (const float*)d_in[5];
    const float* att_dst = (const float*)d_in[6];
    const float* gat_b   = (const float*)d_in[7];
    const float* ln_g    = (const float*)d_in[8];
    const float* ln_b    = (const float*)d_in[9];
    const float* Wo      = (const float*)d_in[10];
    const float* bo      = (const float*)d_in[11];
    float* out = (float*)d_out;

    static bool inited = false;
    static cudaStream_t s1;
    static cudaEvent_t ev0, ev1;
    if (!inited) {
        cudaStreamCreateWithFlags(&s1, cudaStreamNonBlocking);
        cudaEventCreateWithFlags(&ev0, cudaEventDisableTiming);
        cudaEventCreateWithFlags(&ev1, cudaEventDisableTiming);
        cudaFuncSetAttribute(gemm_agg, cudaFuncAttributeMaxDynamicSharedMemorySize, 61440);
        inited = true;
    }

    const int EB4 = (ETOT + 1023) / 1024;
    const int MB  = (NN + 127) / 128;

    // ---- fork: CSR chain on side stream ----
    cudaEventRecord(ev0, 0);
    cudaStreamWaitEvent(s1, ev0, 0);
    hist_kernel<<<EB4, 256, 0, s1>>>(ei);
    scan1_kernel<<<SB, 1024, 0, s1>>>();
    scan3_kernel<<<SB, 1024, 0, s1>>>();
    scatter_kernel<<<EB4, 256, 0, s1>>>(ei);
    cudaEventRecord(ev1, s1);

    // ---- main stream ----
    prep_kernel<<<40 + 256, 256>>>(Wi, Wo, lin_W, att_src, att_dst);
    gemm_in<<<MB, 256>>>(x, bi);

    cudaStreamWaitEvent(0, ev1, 0);

    for (int l = 0; l < NLAY; l++) {
        int last = (l == NLAY - 1);
        agg_h_kernel<<<(NN + 7) / 8, 256>>>();
        gemm_agg<<<MB, 256, last ? 61440 : 36864>>>(gat_b, ln_g, ln_b, l, bo, out, last);
    }
}

// round 17
// speedup vs baseline: 1.1231x; 1.0136x over previous
#include <cuda_runtime.h>
#include <cuda_fp16.h>
#include <cmath>
#include <cstdint>

#define NN   50000
#define EE   800000
#define ETOT 850000
#define INC  128
#define HID  64
#define NH   4
#define HK   256
#define OUTC 40
#define NLAY 4
#define SB   13

// ---------------- device scratch ----------------
__device__ float  g_h[(size_t)NN * HID];
__device__ __half g_hh[(size_t)NN * HID];
__device__ __half g_agg[(size_t)NN * HK];
__device__ float  g_as[(size_t)NN * NH];
__device__ float  g_ad[(size_t)NN * NH];
__device__ float  g_wa[NLAY * 8 * HID];
__device__ __half g_wc[NLAY * NH * HID * HID];
__device__ __half g_wih[INC * HID];
__device__ __half g_woh[HID * 64];
__device__ int    g_deg[NN];          // zero at module load; scan re-zeroes each launch
__device__ int    g_rowptr[NN + 1];
__device__ int    g_erank[ETOT];
__device__ int    g_csrc[ETOT];
__device__ int    g_sync[SB];         // decoupled-lookback words; self-resetting to 0

// ---------------- CSR build ----------------
__global__ void hist_kernel(const int* __restrict__ ei) {
    int e0 = (blockIdx.x * blockDim.x + threadIdx.x) * 4;
    if (e0 >= ETOT) return;
    if (e0 < EE) {
        int4 d4 = *(const int4*)(ei + EE + e0);
        int4 r4;
        r4.x = atomicAdd(&g_deg[d4.x], 1);
        r4.y = atomicAdd(&g_deg[d4.y], 1);
        r4.z = atomicAdd(&g_deg[d4.z], 1);
        r4.w = atomicAdd(&g_deg[d4.w], 1);
        __stcs((int4*)(g_erank + e0), r4);
    } else {
        #pragma unroll
        for (int k = 0; k < 4; k++) {
            int e = e0 + k;
            if (e >= ETOT) return;
            g_erank[e] = atomicAdd(&g_deg[e - EE], 1);
        }
    }
}

// single-pass scan with decoupled lookback (SB=13 blocks, all co-resident)
__global__ void scan_kernel() {
    __shared__ int wsum[32];
    __shared__ int pref_sh;
    int t = threadIdx.x;
    int b = blockIdx.x;
    int i0 = b * 4096 + t * 4;
    int4 v = make_int4(0, 0, 0, 0);
    if (i0 + 3 < NN) {
        v = *(const int4*)(g_deg + i0);
        *(int4*)(g_deg + i0) = make_int4(0, 0, 0, 0);
    } else {
        if (i0 + 0 < NN) { v.x = g_deg[i0 + 0]; g_deg[i0 + 0] = 0; }
        if (i0 + 1 < NN) { v.y = g_deg[i0 + 1]; g_deg[i0 + 1] = 0; }
        if (i0 + 2 < NN) { v.z = g_deg[i0 + 2]; g_deg[i0 + 2] = 0; }
        if (i0 + 3 < NN) { v.w = g_deg[i0 + 3]; g_deg[i0 + 3] = 0; }
    }
    int tot = v.x + v.y + v.z + v.w;
    int x = tot;
    #pragma unroll
    for (int s = 1; s < 32; s <<= 1) {
        int y = __shfl_up_sync(0xFFFFFFFFu, x, s);
        if ((t & 31) >= s) x += y;
    }
    if ((t & 31) == 31) wsum[t >> 5] = x;
    __syncthreads();
    if (t < 32) {
        int y = wsum[t];
        #pragma unroll
        for (int s = 1; s < 32; s <<= 1) {
            int z = __shfl_up_sync(0xFFFFFFFFu, y, s);
            if (t >= s) y += z;
        }
        wsum[t] = y;
    }
    __syncthreads();
    int blk_tot = wsum[31];

    // lookback: obtain exclusive prefix of this block
    if (t == 0) {
        int pref = 0;
        if (b > 0) {
            int vflag;
            do { vflag = atomicAdd(&g_sync[b - 1], 0); } while (vflag == 0);
            pref = vflag - 1;
            atomicExch(&g_sync[b - 1], 0);   // self-reset for next launch (read exactly once)
        }
        if (b < SB - 1)
            atomicExch(&g_sync[b], pref + blk_tot + 1);
        pref_sh = pref;
        if (b == SB - 1) g_rowptr[NN] = pref + blk_tot;
    }
    __syncthreads();
    int base = pref_sh;

    int excl = base + x - tot + ((t >= 32) ? wsum[(t >> 5) - 1] : 0);
    if (i0 + 3 < NN) {
        *(int4*)(g_rowptr + i0) =
            make_int4(excl, excl + v.x, excl + v.x + v.y, excl + v.x + v.y + v.z);
    } else {
        if (i0 + 0 < NN) g_rowptr[i0 + 0] = excl;
        if (i0 + 1 < NN) g_rowptr[i0 + 1] = excl + v.x;
        if (i0 + 2 < NN) g_rowptr[i0 + 2] = excl + v.x + v.y;
        if (i0 + 3 < NN) g_rowptr[i0 + 3] = excl + v.x + v.y + v.z;
    }
}

// scatter: atomic-free — position = rowptr[dst] + rank; streaming hints
__global__ void scatter_kernel(const int* __restrict__ ei) {
    int e0 = (blockIdx.x * blockDim.x + threadIdx.x) * 4;
    if (e0 >= ETOT) return;
    if (e0 < EE) {
        int4 s4 = __ldcs((const int4*)(ei + e0));
        int4 d4 = __ldcs((const int4*)(ei + EE + e0));
        int4 r4 = __ldcs((const int4*)(g_erank + e0));
        __stcs(g_csrc + g_rowptr[d4.x] + r4.x, s4.x);
        __stcs(g_csrc + g_rowptr[d4.y] + r4.y, s4.y);
        __stcs(g_csrc + g_rowptr[d4.z] + r4.z, s4.z);
        __stcs(g_csrc + g_rowptr[d4.w] + r4.w, s4.w);
    } else {
        #pragma unroll
        for (int k = 0; k < 4; k++) {
            int e = e0 + k;
            if (e >= ETOT) return;
            int n = e - EE;
            __stcs(g_csrc + g_rowptr[n] + g_erank[e], n);
        }
    }
}

// ---------------- fused prep ----------------
__global__ void prep_kernel(const float* __restrict__ Wi,
                            const float* __restrict__ Wo,
                            const float* __restrict__ lin_W,
                            const float* __restrict__ att_src,
                            const float* __restrict__ att_dst) {
    int b = blockIdx.x, t = threadIdx.x;
    if (b < 32) {
        int i = b * 256 + t;
        if (i < INC * HID) g_wih[i] = __float2half(Wi[i]);
        if (i < HID * 64) {
            int k = i >> 6, c = i & 63;
            g_woh[i] = __float2half(c < OUTC ? Wo[k * OUTC + c] : 0.f);
        }
    } else if (b < 40) {
        int tid = (b - 32) * 256 + t;
        if (tid >= NLAY * 8 * HID) return;
        int k = tid & 63;
        int v = (tid >> 6) & 7;
        int l = tid >> 9;
        int h = v & 3;
        const float* att  = (v < 4) ? att_src : att_dst;
        const float* wrow = lin_W + (size_t)l * HID * HK + (size_t)k * HK + h * HID;
        const float* arow = att + l * HK + h * HID;
        float s = 0.f;
        #pragma unroll
        for (int c = 0; c < HID; c++) s += wrow[c] * arow[c];
        g_wa[tid] = s;
    } else {
        int tid = (b - 40) * 256 + t;
        if (tid >= NLAY * NH * HID * HID) return;
        int c = tid & 63;
        int k = (tid >> 6) & 63;
        int h = (tid >> 12) & 3;
        int l = tid >> 14;
        g_wc[tid] = __float2half(0.25f * lin_W[(size_t)l * HID * HK + (size_t)k * HK + h * HID + c]);
    }
}

// ---------------- MMA input GEMM (reads fp32 x directly) + fused layer-0 alpha ----------------
__global__ void gemm_in(const float* __restrict__ x, const float* __restrict__ bi) {
    __shared__ alignas(16) char buf[49152];
    __half* Asm = (__half*)buf;
    __half* Bsm = (__half*)(buf + 32768);
    float*  Cs  = (float*)buf;
    float*  wa_sm = (float*)(buf + 47104);

    int t = threadIdx.x;
    int m0 = blockIdx.x << 7;
    #pragma unroll
    for (int i = 0; i < 8; i++) {
        int cid = t + i * 256;
        int r = cid >> 4, c = cid & 15;
        __half2 hv[4] = {};
        if (m0 + r < NN) {
            const float* src = x + (size_t)(m0 + r) * INC + (c << 3);
            float4 f0 = *(const float4*)src;
            float4 f1 = *(const float4*)(src + 4);
            hv[0] = __floats2half2_rn(f0.x, f0.y);
            hv[1] = __floats2half2_rn(f0.z, f0.w);
            hv[2] = __floats2half2_rn(f1.x, f1.y);
            hv[3] = __floats2half2_rn(f1.z, f1.w);
        }
        *(uint4*)(Asm + r * 128 + ((c ^ (r & 7)) << 3)) = *(uint4*)hv;
    }
    #pragma unroll
    for (int i = 0; i < 4; i++) {
        int cid = t + i * 256;
        int k = cid >> 3, c = cid & 7;
        uint4 v = *(const uint4*)(g_wih + k * 64 + (c << 3));
        *(uint4*)(Bsm + k * 64 + ((c ^ (k & 7)) << 3)) = v;
    }
    __syncthreads();

    int wid = t >> 5, lane = t & 31;
    int wm = (wid & 3) << 5;
    int wn = (wid >> 2) << 5;
    float c[2][4][4] = {};

    #pragma unroll
    for (int ks = 0; ks < 8; ks++) {
        uint32_t a[2][4];
        #pragma unroll
        for (int mt = 0; mt < 2; mt++) {
            int row = wm + (mt << 4) + (lane & 15);
            int chunk = (ks << 1) + (lane >> 4);
            uint32_t addr = (uint32_t)__cvta_generic_to_shared(
                Asm + row * 128 + ((chunk ^ (row & 7)) << 3));
            asm volatile("ldmatrix.sync.aligned.m8n8.x4.shared.b16 {%0,%1,%2,%3}, [%4];"
                         : "=r"(a[mt][0]), "=r"(a[mt][1]), "=r"(a[mt][2]), "=r"(a[mt][3])
                         : "r"(addr));
        }
        uint32_t b[4][2];
        #pragma unroll
        for (int nt2 = 0; nt2 < 2; nt2++) {
            int krow = (ks << 4) + (lane & 15);
            int nchunk = ((wn + (nt2 << 4)) >> 3) + (lane >> 4);
            uint32_t addr = (uint32_t)__cvta_generic_to_shared(
                Bsm + krow * 64 + ((nchunk ^ (krow & 7)) << 3));
            uint32_t r0, r1, r2, r3;
            asm volatile("ldmatrix.sync.aligned.m8n8.x4.trans.shared.b16 {%0,%1,%2,%3}, [%4];"
                         : "=r"(r0), "=r"(r1), "=r"(r2), "=r"(r3)
                         : "r"(addr));
            b[nt2 * 2 + 0][0] = r0; b[nt2 * 2 + 0][1] = r1;
            b[nt2 * 2 + 1][0] = r2; b[nt2 * 2 + 1][1] = r3;
        }
        #pragma unroll
        for (int mt = 0; mt < 2; mt++)
            #pragma unroll
            for (int nt = 0; nt < 4; nt++)
                asm volatile(
                    "mma.sync.aligned.m16n8k16.row.col.f32.f16.f16.f32 "
                    "{%0,%1,%2,%3},{%4,%5,%6,%7},{%8,%9},{%0,%1,%2,%3};"
                    : "+f"(c[mt][nt][0]), "+f"(c[mt][nt][1]),
                      "+f"(c[mt][nt][2]), "+f"(c[mt][nt][3])
                    : "r"(a[mt][0]), "r"(a[mt][1]), "r"(a[mt][2]), "r"(a[mt][3]),
                      "r"(b[nt][0]), "r"(b[nt][1]));
    }

    __syncthreads();
    #pragma unroll
    for (int i = 0; i < 2; i++)
        wa_sm[t + i * 256] = g_wa[t + i * 256];

    int rg = lane >> 2, cg = (lane & 3) << 1;
    #pragma unroll
    for (int nt = 0; nt < 4; nt++) {
        int col = wn + (nt << 3) + cg;
        float b0 = bi[col], b1 = bi[col + 1];
        #pragma unroll
        for (int mt = 0; mt < 2; mt++) {
            #pragma unroll
            for (int half_ = 0; half_ < 2; half_++) {
                int rl = wm + (mt << 4) + rg + half_ * 8;
                int r = m0 + rl;
                float v0 = c[mt][nt][half_ * 2 + 0] + b0;
                float v1 = c[mt][nt][half_ * 2 + 1] + b1;
                v0 = v0 > 0.f ? v0 : expm1f(v0);
                v1 = v1 > 0.f ? v1 : expm1f(v1);
                Cs[rl * 68 + col]     = v0;
                Cs[rl * 68 + col + 1] = v1;
                if (r < NN) {
                    *(float2*)(g_h + (size_t)r * HID + col) = make_float2(v0, v1);
                    *(__half2*)(g_hh + (size_t)r * HID + col) = __floats2half2_rn(v0, v1);
                }
            }
        }
    }
    __syncthreads();

    {
        int r = t >> 1, hs = t & 1;
        int n = m0 + r;
        if (n < NN) {
            const float* wv = wa_sm + hs * 4 * 64;
            float a0 = 0.f, a1 = 0.f, a2 = 0.f, a3 = 0.f;
            #pragma unroll
            for (int cc = 0; cc < 64; cc++) {
                float hv = Cs[r * 68 + cc];
                a0 += hv * wv[cc];
                a1 += hv * wv[64 + cc];
                a2 += hv * wv[128 + cc];
                a3 += hv * wv[192 + cc];
            }
            float* dst = (hs == 0 ? g_as : g_ad) + 4 * (size_t)n;
            *(float4*)dst = make_float4(a0, a1, a2, a3);
        }
    }
}

// ---------------- aggregation in h-space (R6 exact) ----------------
__global__ void agg_h_kernel() {
    __shared__ float sp[8][32][4];
    int wl   = threadIdx.x >> 5;
    int w    = (blockIdx.x * blockDim.x + threadIdx.x) >> 5;
    int lane = threadIdx.x & 31;
    if (w >= NN) return;

    float4 ad4 = *(const float4*)(g_ad + 4 * (size_t)w);

    float acc[4][2] = {};
    float denl[4] = {};
    int beg = g_rowptr[w], end = g_rowptr[w + 1];

    for (int base = beg; base < end; base += 32) {
        int idx = base + lane;
        bool valid = idx < end;
        int sv = valid ? g_csrc[idx] : 0;
        float4 as4 = *(const float4*)(g_as + 4 * (size_t)sv);
        float p0, p1, p2, p3;
        {
            float e0 = as4.x + ad4.x, e1 = as4.y + ad4.y;
            float e2 = as4.z + ad4.z, e3 = as4.w + ad4.w;
            e0 = e0 > 0.f ? e0 : 0.2f * e0;
            e1 = e1 > 0.f ? e1 : 0.2f * e1;
            e2 = e2 > 0.f ? e2 : 0.2f * e2;
            e3 = e3 > 0.f ? e3 : 0.2f * e3;
            p0 = valid ? __expf(e0) : 0.f;
            p1 = valid ? __expf(e1) : 0.f;
            p2 = valid ? __expf(e2) : 0.f;
            p3 = valid ? __expf(e3) : 0.f;
        }
        denl[0] += p0; denl[1] += p1; denl[2] += p2; denl[3] += p3;
        *(float4*)&sp[wl][lane][0] = make_float4(p0, p1, p2, p3);
        __syncwarp();

        int m = end - base; if (m > 32) m = 32;
        int j = 0;
        for (; j + 1 < m; j += 2) {
            int sA = __shfl_sync(0xFFFFFFFFu, sv, j);
            int sB = __shfl_sync(0xFFFFFFFFu, sv, j + 1);
            float4 pA = *(const float4*)&sp[wl][j][0];
            float4 pB = *(const float4*)&sp[wl][j + 1][0];
            __half2 hA = *(const __half2*)(g_hh + (size_t)sA * HID + 2 * lane);
            __half2 hB = *(const __half2*)(g_hh + (size_t)sB * HID + 2 * lane);
            float2 fA = __half22float2(hA);
            float2 fB = __half22float2(hB);
            acc[0][0] += pA.x * fA.x + pB.x * fB.x;
            acc[0][1] += pA.x * fA.y + pB.x * fB.y;
            acc[1][0] += pA.y * fA.x + pB.y * fB.x;
            acc[1][1] += pA.y * fA.y + pB.y * fB.y;
            acc[2][0] += pA.z * fA.x + pB.z * fB.x;
            acc[2][1] += pA.z * fA.y + pB.z * fB.y;
            acc[3][0] += pA.w * fA.x + pB.w * fB.x;
            acc[3][1] += pA.w * fA.y + pB.w * fB.y;
        }
        if (j < m) {
            int s = __shfl_sync(0xFFFFFFFFu, sv, j);
            float4 pj = *(const float4*)&sp[wl][j][0];
            __half2 hv = *(const __half2*)(g_hh + (size_t)s * HID + 2 * lane);
            float2 f = __half22float2(hv);
            acc[0][0] += pj.x * f.x; acc[0][1] += pj.x * f.y;
            acc[1][0] += pj.y * f.x; acc[1][1] += pj.y * f.y;
            acc[2][0] += pj.z * f.x; acc[2][1] += pj.z * f.y;
            acc[3][0] += pj.w * f.x; acc[3][1] += pj.w * f.y;
        }
        __syncwarp();
    }

    #pragma unroll
    for (int h = 0; h < 4; h++) {
        float d = denl[h];
        #pragma unroll
        for (int s = 16; s > 0; s >>= 1)
            d += __shfl_xor_sync(0xFFFFFFFFu, d, s);
        denl[h] = 1.f / (d + 1e-16f);
    }

    __half* ap = g_agg + (size_t)w * HK;
    #pragma unroll
    for (int h = 0; h < 4; h++) {
        *(__half2*)(ap + h * HID + 2 * lane) =
            __floats2half2_rn(acc[h][0] * denl[h], acc[h][1] * denl[h]);
    }
}

// ---------------- MMA head-mix GEMM + epilogue + next-layer alpha + (last) output GEMM ----------------
__global__ void gemm_agg(const float* __restrict__ gat_b,
                         const float* __restrict__ ln_g,
                         const float* __restrict__ ln_b, int layer,
                         const float* __restrict__ bo, float* __restrict__ out,
                         int last) {
    extern __shared__ char buf[];
    __half* Asm = (__half*)buf;
    __half* Bsm = (__half*)(buf + 16384);
    float*  Cs  = (float*)buf;
    float*  wa_sm = (float*)(buf + 34816);

    int t  = threadIdx.x;
    int m0 = blockIdx.x << 7;
    int wid = t >> 5, lane = t & 31;
    int wm = (wid & 3) << 5;
    int wn = (wid >> 2) << 5;
    bool do_alpha = (layer + 1 < NLAY);

    if (do_alpha) {
        #pragma unroll
        for (int i = 0; i < 2; i++)
            wa_sm[t + i * 256] = g_wa[(layer + 1) * 512 + t + i * 256];
    }

    float c[2][4][4] = {};

    for (int h = 0; h < 4; h++) {
        if (h) __syncthreads();
        #pragma unroll
        for (int i = 0; i < 4; i++) {
            int cid = t + i * 256;
            int r = cid >> 3, cc = cid & 7;
            uint4 v = make_uint4(0, 0, 0, 0);
            if (m0 + r < NN)
                v = *(const uint4*)(g_agg + (size_t)(m0 + r) * HK + h * HID + (cc << 3));
            *(uint4*)(Asm + r * 64 + ((cc ^ (r & 7)) << 3)) = v;
        }
        const __half* wb = g_wc + (size_t)(layer * 4 + h) * HID * HID;
        #pragma unroll
        for (int i = 0; i < 2; i++) {
            int cid = t + i * 256;
            int k = cid >> 3, cc = cid & 7;
            uint4 v = *(const uint4*)(wb + k * 64 + (cc << 3));
            *(uint4*)(Bsm + k * 64 + ((cc ^ (k & 7)) << 3)) = v;
        }
        __syncthreads();

        #pragma unroll
        for (int ks = 0; ks < 4; ks++) {
            uint32_t a[2][4];
            #pragma unroll
            for (int mt = 0; mt < 2; mt++) {
                int row = wm + (mt << 4) + (lane & 15);
                int chunk = (ks << 1) + (lane >> 4);
                uint32_t addr = (uint32_t)__cvta_generic_to_shared(
                    Asm + row * 64 + ((chunk ^ (row & 7)) << 3));
                asm volatile("ldmatrix.sync.aligned.m8n8.x4.shared.b16 {%0,%1,%2,%3}, [%4];"
                             : "=r"(a[mt][0]), "=r"(a[mt][1]), "=r"(a[mt][2]), "=r"(a[mt][3])
                             : "r"(addr));
            }
            uint32_t b[4][2];
            #pragma unroll
            for (int nt2 = 0; nt2 < 2; nt2++) {
                int krow = (ks << 4) + (lane & 15);
                int nchunk = ((wn + (nt2 << 4)) >> 3) + (lane >> 4);
                uint32_t addr = (uint32_t)__cvta_generic_to_shared(
                    Bsm + krow * 64 + ((nchunk ^ (krow & 7)) << 3));
                uint32_t r0, r1, r2, r3;
                asm volatile("ldmatrix.sync.aligned.m8n8.x4.trans.shared.b16 {%0,%1,%2,%3}, [%4];"
                             : "=r"(r0), "=r"(r1), "=r"(r2), "=r"(r3)
                             : "r"(addr));
                b[nt2 * 2 + 0][0] = r0; b[nt2 * 2 + 0][1] = r1;
                b[nt2 * 2 + 1][0] = r2; b[nt2 * 2 + 1][1] = r3;
            }
            #pragma unroll
            for (int mt = 0; mt < 2; mt++)
                #pragma unroll
                for (int nt = 0; nt < 4; nt++)
                    asm volatile(
                        "mma.sync.aligned.m16n8k16.row.col.f32.f16.f16.f32 "
                        "{%0,%1,%2,%3},{%4,%5,%6,%7},{%8,%9},{%0,%1,%2,%3};"
                        : "+f"(c[mt][nt][0]), "+f"(c[mt][nt][1]),
                          "+f"(c[mt][nt][2]), "+f"(c[mt][nt][3])
                        : "r"(a[mt][0]), "r"(a[mt][1]), "r"(a[mt][2]), "r"(a[mt][3]),
                          "r"(b[nt][0]), "r"(b[nt][1]));
        }
    }

    __syncthreads();
    int rg = lane >> 2, cg = (lane & 3) << 1;
    #pragma unroll
    for (int mt = 0; mt < 2; mt++) {
        int r = wm + (mt << 4) + rg;
        #pragma unroll
        for (int nt = 0; nt < 4; nt++) {
            int col = wn + (nt << 3) + cg;
            Cs[r * 68 + col]       = c[mt][nt][0];
            Cs[r * 68 + col + 1]   = c[mt][nt][1];
            Cs[(r + 8) * 68 + col]     = c[mt][nt][2];
            Cs[(r + 8) * 68 + col + 1] = c[mt][nt][3];
        }
    }
    __syncthreads();

    float2 gbv = *(const float2*)(gat_b + layer * HID + 2 * lane);
    float2 ggv = *(const float2*)(ln_g  + layer * HID + 2 * lane);
    float2 lbv = *(const float2*)(ln_b  + layer * HID + 2 * lane);
    for (int rr = 0; rr < 16; rr++) {
        int r = wid * 16 + rr;
        int n = m0 + r;
        if (n >= NN) break;
        float v0 = Cs[r * 68 + 2 * lane]     + gbv.x;
        float v1 = Cs[r * 68 + 2 * lane + 1] + gbv.y;
        float sum = v0 + v1, sq = v0 * v0 + v1 * v1;
        #pragma unroll
        for (int s = 16; s > 0; s >>= 1) {
            sum += __shfl_xor_sync(0xFFFFFFFFu, sum, s);
            sq  += __shfl_xor_sync(0xFFFFFFFFu, sq, s);
        }
        float mu   = sum * (1.f / 64.f);
        float var  = sq * (1.f / 64.f) - mu * mu;
        float rstd = rsqrtf(var + 1e-5f);
        v0 = (v0 - mu) * rstd * ggv.x + lbv.x;
        v1 = (v1 - mu) * rstd * ggv.y + lbv.y;
        v0 = v0 > 0.f ? v0 : expm1f(v0);
        v1 = v1 > 0.f ? v1 : expm1f(v1);
        float* hp = g_h + (size_t)n * HID + 2 * lane;
        if (layer > 0) {
            float2 rv = *(const float2*)hp;
            v0 += rv.x; v1 += rv.y;
        }
        Cs[r * 68 + 2 * lane]     = v0;
        Cs[r * 68 + 2 * lane + 1] = v1;
        *(float2*)hp = make_float2(v0, v1);
        *(__half2*)(g_hh + (size_t)n * HID + 2 * lane) = __floats2half2_rn(v0, v1);
    }

    if (do_alpha) {
        __syncthreads();
        int r = t >> 1, hs = t & 1;
        int n = m0 + r;
        if (n < NN) {
            const float* wv = wa_sm + hs * 4 * 64;
            float a0 = 0.f, a1 = 0.f, a2 = 0.f, a3 = 0.f;
            #pragma unroll
            for (int cc = 0; cc < 64; cc++) {
                float hv = Cs[r * 68 + cc];
                a0 += hv * wv[cc];
                a1 += hv * wv[64 + cc];
                a2 += hv * wv[128 + cc];
                a3 += hv * wv[192 + cc];
            }
            float* dst = (hs == 0 ? g_as : g_ad) + 4 * (size_t)n;
            *(float4*)dst = make_float4(a0, a1, a2, a3);
        }
    }

    if (last) {
        __half* Asm2 = (__half*)(buf + 36864);
        __half* Bsm2 = (__half*)(buf + 53248);
        __syncthreads();
        #pragma unroll
        for (int i = 0; i < 4; i++) {
            int cid = t + i * 256;
            int r = cid >> 3, cc = cid & 7;
            const float* src = Cs + r * 68 + (cc << 3);
            __half2 hv[4];
            hv[0] = __floats2half2_rn(src[0], src[1]);
            hv[1] = __floats2half2_rn(src[2], src[3]);
            hv[2] = __floats2half2_rn(src[4], src[5]);
            hv[3] = __floats2half2_rn(src[6], src[7]);
            *(uint4*)(Asm2 + r * 64 + ((cc ^ (r & 7)) << 3)) = *(uint4*)hv;
        }
        #pragma unroll
        for (int i = 0; i < 2; i++) {
            int cid = t + i * 256;
            int k = cid >> 3, cc = cid & 7;
            uint4 v = *(const uint4*)(g_woh + k * 64 + (cc << 3));
            *(uint4*)(Bsm2 + k * 64 + ((cc ^ (k & 7)) << 3)) = v;
        }
        __syncthreads();

        float co[2][4][4] = {};
        #pragma unroll
        for (int ks = 0; ks < 4; ks++) {
            uint32_t a[2][4];
            #pragma unroll
            for (int mt = 0; mt < 2; mt++) {
                int row = wm + (mt << 4) + (lane & 15);
                int chunk = (ks << 1) + (lane >> 4);
                uint32_t addr = (uint32_t)__cvta_generic_to_shared(
                    Asm2 + row * 64 + ((chunk ^ (row & 7)) << 3));
                asm volatile("ldmatrix.sync.aligned.m8n8.x4.shared.b16 {%0,%1,%2,%3}, [%4];"
                             : "=r"(a[mt][0]), "=r"(a[mt][1]), "=r"(a[mt][2]), "=r"(a[mt][3])
                             : "r"(addr));
            }
            uint32_t b[4][2];
            #pragma unroll
            for (int nt2 = 0; nt2 < 2; nt2++) {
                int krow = (ks << 4) + (lane & 15);
                int nchunk = ((wn + (nt2 << 4)) >> 3) + (lane >> 4);
                uint32_t addr = (uint32_t)__cvta_generic_to_shared(
                    Bsm2 + krow * 64 + ((nchunk ^ (krow & 7)) << 3));
                uint32_t r0, r1, r2, r3;
                asm volatile("ldmatrix.sync.aligned.m8n8.x4.trans.shared.b16 {%0,%1,%2,%3}, [%4];"
                             : "=r"(r0), "=r"(r1), "=r"(r2), "=r"(r3)
                             : "r"(addr));
                b[nt2 * 2 + 0][0] = r0; b[nt2 * 2 + 0][1] = r1;
                b[nt2 * 2 + 1][0] = r2; b[nt2 * 2 + 1][1] = r3;
            }
            #pragma unroll
            for (int mt = 0; mt < 2; mt++)
                #pragma unroll
                for (int nt = 0; nt < 4; nt++)
                    asm volatile(
                        "mma.sync.aligned.m16n8k16.row.col.f32.f16.f16.f32 "
                        "{%0,%1,%2,%3},{%4,%5,%6,%7},{%8,%9},{%0,%1,%2,%3};"
                        : "+f"(co[mt][nt][0]), "+f"(co[mt][nt][1]),
                          "+f"(co[mt][nt][2]), "+f"(co[mt][nt][3])
                        : "r"(a[mt][0]), "r"(a[mt][1]), "r"(a[mt][2]), "r"(a[mt][3]),
                          "r"(b[nt][0]), "r"(b[nt][1]));
        }

        #pragma unroll
        for (int nt = 0; nt < 4; nt++) {
            int col = wn + (nt << 3) + cg;
            if (col >= OUTC) continue;
            float b0 = bo[col], b1 = bo[col + 1];
            #pragma unroll
            for (int mt = 0; mt < 2; mt++) {
                #pragma unroll
                for (int half_ = 0; half_ < 2; half_++) {
                    int r = m0 + wm + (mt << 4) + rg + half_ * 8;
                    if (r >= NN) continue;
                    *(float2*)(out + (size_t)r * OUTC + col) =
                        make_float2(co[mt][nt][half_ * 2 + 0] + b0,
                                    co[mt][nt][half_ * 2 + 1] + b1);
                }
            }
        }
    }
}

// ---------------- host orchestration ----------------
extern "C" void kernel_launch(void* const* d_in, const int* in_sizes, int n_in,
                              void* d_out, int out_size) {
    const float* x       = (const float*)d_in[0];
    const int*   ei      = (const int*)d_in[1];
    const float* Wi      = (const float*)d_in[2];
    const float* bi      = (const float*)d_in[3];
    const float* lin_W   = (const float*)d_in[4];
    const float* att_src = (const float*)d_in[5];
    const float* att_dst = (const float*)d_in[6];
    const float* gat_b   = (const float*)d_in[7];
    const float* ln_g    = (const float*)d_in[8];
    const float* ln_b    = (const float*)d_in[9];
    const float* Wo      = (const float*)d_in[10];
    const float* bo      = (const float*)d_in[11];
    float* out = (float*)d_out;

    static bool inited = false;
    static cudaStream_t s1;
    static cudaEvent_t ev0, ev1;
    if (!inited) {
        cudaStreamCreateWithFlags(&s1, cudaStreamNonBlocking);
        cudaEventCreateWithFlags(&ev0, cudaEventDisableTiming);
        cudaEventCreateWithFlags(&ev1, cudaEventDisableTiming);
        cudaFuncSetAttribute(gemm_agg, cudaFuncAttributeMaxDynamicSharedMemorySize, 61440);
        inited = true;
    }

    const int EB4 = (ETOT + 1023) / 1024;
    const int MB  = (NN + 127) / 128;

    // ---- fork: CSR chain on side stream ----
    cudaEventRecord(ev0, 0);
    cudaStreamWaitEvent(s1, ev0, 0);
    hist_kernel<<<EB4, 256, 0, s1>>>(ei);
    scan_kernel<<<SB, 1024, 0, s1>>>();
    scatter_kernel<<<EB4, 256, 0, s1>>>(ei);
    cudaEventRecord(ev1, s1);

    // ---- main stream ----
    prep_kernel<<<40 + 256, 256>>>(Wi, Wo, lin_W, att_src, att_dst);
    gemm_in<<<MB, 256>>>(x, bi);

    cudaStreamWaitEvent(0, ev1, 0);

    for (int l = 0; l < NLAY; l++) {
        int last = (l == NLAY - 1);
        agg_h_kernel<<<(NN + 7) / 8, 256>>>();
        gemm_agg<<<MB, 256, last ? 61440 : 36864>>>(gat_b, ln_g, ln_b, l, bo, out, last);
    }
}